// round 8
// baseline (speedup 1.0000x reference)
#include <cuda_runtime.h>
#include <cuda_fp16.h>
#include <cstdint>
#include <cstddef>

#define TLEN 4096
#define NB   32
#define HD   256
#define HS   264   // smem halves per n-row (256 + 8 pad)

// Scratch (device globals: allocation-free rule)
static __device__ __align__(256) float  g_Xp0[(size_t)TLEN * NB * HD]; // frag-layout preacts L0
static __device__ __align__(256) float  g_Xp1[(size_t)TLEN * NB * HD]; // frag-layout preacts L1
static __device__ __align__(256) __half g_H0h[(size_t)TLEN * NB * HD]; // L0 hidden, [t][cid][n][256] fp16
static __device__ int g_progA[8];   // [cid*2 + rank]
static __device__ int g_progB[8];

// ---------------------------------------------------------------------------
__device__ __forceinline__ float tanh_mufu(float x) {
    float y;
    asm("tanh.approx.f32 %0, %1;" : "=f"(y) : "f"(x));
    return y;
}
__device__ __forceinline__ uint32_t pack_h2(float lo, float hi) {
    __half2 h = __floats2half2_rn(lo, hi);
    return *reinterpret_cast<uint32_t*>(&h);
}
__device__ __forceinline__ uint32_t smem_u32(const void* p) {
    uint32_t a;
    asm("{ .reg .u64 t; cvta.to.shared.u64 t, %1; cvt.u32.u64 %0, t; }" : "=r"(a) : "l"(p));
    return a;
}
__device__ __forceinline__ uint32_t mapa_u32(uint32_t a, uint32_t r) {
    uint32_t d;
    asm("mapa.shared::cluster.u32 %0, %1, %2;" : "=r"(d) : "r"(a), "r"(r));
    return d;
}
__device__ __forceinline__ int ld_acq(const int* p) {
    int v;
    asm volatile("ld.acquire.gpu.global.s32 %0, [%1];" : "=r"(v) : "l"(p));
    return v;
}
__device__ __forceinline__ void st_rel(int* p, int v) {
    asm volatile("st.release.gpu.global.s32 [%0], %1;" :: "l"(p), "r"(v));
}
__device__ __forceinline__ void st_cluster16(uint32_t addr, __half h) {
    unsigned short u = __half_as_ushort(h);
    asm volatile("st.shared::cluster.b16 [%0], %1;" :: "r"(addr), "h"(u) : "memory");
}
__device__ __forceinline__ void mbar_init(uint32_t addr, uint32_t cnt) {
    asm volatile("mbarrier.init.shared.b64 [%0], %1;" :: "r"(addr), "r"(cnt) : "memory");
}
__device__ __forceinline__ void mbar_arrive_peer(uint32_t addr) {
    asm volatile("mbarrier.arrive.release.cluster.shared::cluster.b64 _, [%0];"
                 :: "r"(addr) : "memory");
}
__device__ __forceinline__ void mbar_wait(uint32_t addr, uint32_t parity) {
    asm volatile(
        "{\n\t.reg .pred P;\n\t"
        "W_%=:\n\t"
        "mbarrier.try_wait.parity.acquire.cluster.shared::cta.b64 P, [%0], %1, 0x989680;\n\t"
        "@P bra.uni D_%=;\n\t"
        "bra.uni W_%=;\n\t"
        "D_%=:\n\t}"
        :: "r"(addr), "r"(parity) : "memory");
}
#define CLUSTER_SYNC() do {                                              \
    asm volatile("barrier.cluster.arrive.aligned;" ::: "memory");        \
    asm volatile("barrier.cluster.wait.aligned;" ::: "memory");          \
} while (0)

#define HMMA(acc, af, bf0, bf1)                                               \
    asm volatile(                                                             \
        "mma.sync.aligned.m16n8k16.row.col.f32.f16.f16.f32 "                  \
        "{%0,%1,%2,%3}, {%4,%5,%6,%7}, {%8,%9}, {%0,%1,%2,%3};"               \
        : "+f"((acc)[0]), "+f"((acc)[1]), "+f"((acc)[2]), "+f"((acc)[3])      \
        : "r"((af)[0]), "r"((af)[1]), "r"((af)[2]), "r"((af)[3]),             \
          "r"(bf0), "r"(bf1))
#define LDSM4(r0, r1, r2, r3, a)                                              \
    asm volatile("ldmatrix.sync.aligned.m8n8.x4.shared.b16 {%0,%1,%2,%3}, [%4];" \
        : "=r"(r0), "=r"(r1), "=r"(r2), "=r"(r3) : "r"(a))

// One M=16 tile x full K=256: 16 HMMAs, B frags via ldmatrix from byte addr ab.
#define MMA_STEP16(c, c2, afr, ab)                                            \
    do {                                                                      \
        _Pragma("unroll")                                                     \
        for (int kk = 0; kk < 8; ++kk) {                                      \
            uint32_t b0, b1, b2, b3;                                          \
            LDSM4(b0, b1, b2, b3, (ab) + kk * 64);                            \
            HMMA((c),  (afr)[2 * kk],     b0, b1);                            \
            HMMA((c2), (afr)[2 * kk + 1], b2, b3);                            \
        }                                                                     \
    } while (0)

// Register-resident A fragments for a 16-row slice (rows r0, r0+8) of 256x256 fp32 W.
__device__ __forceinline__ void load_frags16(uint32_t afr[16][4],
                                             const float* __restrict__ W,
                                             int r0, int tid4) {
    #pragma unroll
    for (int kt = 0; kt < 16; ++kt) {
        const int k0 = kt * 16 + tid4 * 2;
        const float* p0 = W + (size_t)r0 * HD + k0;
        const float* p1 = W + (size_t)(r0 + 8) * HD + k0;
        afr[kt][0] = pack_h2(p0[0], p0[1]);
        afr[kt][1] = pack_h2(p1[0], p1[1]);
        afr[kt][2] = pack_h2(p0[8], p0[9]);
        afr[kt][3] = pack_h2(p1[8], p1[9]);
    }
}

// ---------------------------------------------------------------------------
// Fused 3-stage pipelined kernel, 2-CTA clusters splitting M=256 -> 128 each.
// grid = 24 CTAs = 12 clusters: A (cl 0-3), B (cl 4-7), C (cl 8-11).
__global__ void __cluster_dims__(2, 1, 1) __launch_bounds__(256, 1)
rnn_fused_kernel(
    const float* __restrict__ Whh0, const float* __restrict__ Whh1,
    const float* __restrict__ Wih1,
    const float* __restrict__ b_ih, const float* __restrict__ b_hh,
    const float* __restrict__ h0all, float* __restrict__ Out)
{
    __shared__ __align__(16) __half hsA[2][8][HS];    // h state / B staging
    __shared__ __align__(16) float  obuf[2][8][136];  // C: output staging (half width)
    __shared__ __align__(8)  unsigned long long mbar[2];

    const int tid  = threadIdx.x;
    const int w    = tid >> 5;
    const int lane = tid & 31;
    const int grp  = lane >> 2;
    const int tid4 = lane & 3;

    uint32_t crank;
    asm("mov.u32 %0, %%cluster_ctarank;" : "=r"(crank));
    const uint32_t peer = crank ^ 1;
    const int clid = blockIdx.x >> 1;
    const int role = clid >> 2;          // 0=A, 1=B, 2=C
    const int cid  = clid & 3;
    const int b0   = cid * 8;
    const int n0   = tid4 * 2;
    const int hloc = w * 16 + grp;              // 0..127 within rank half
    const int hbase = (int)crank * 128 + hloc;  // global hidden index

    const uint32_t hs_base = smem_u32(&hsA[0][0][0]);
    const uint32_t lsm0 = hs_base + (uint32_t)(lane & 7) * (HS * 2) + (uint32_t)(lane >> 3) * 16;
    const uint32_t BUFB = 8 * HS * 2;
    const uint32_t mb0      = smem_u32(&mbar[0]);
    const uint32_t mb_peer0 = mapa_u32(mb0, peer);
    const uint32_t rbase    = mapa_u32(hs_base, peer);

    if (tid == 0) { mbar_init(mb0, 1); mbar_init(mb0 + 8, 1); }
    __syncthreads();
    CLUSTER_SYNC();   // peer mbarriers initialized before any arrive

    // ======================= Stage A: layer-0 recurrence ====================
    if (role == 0) {
        uint32_t afr[16][4];
        load_frags16(afr, Whh0, hbase, tid4);

        for (int idx = tid; idx < 8 * HD; idx += 256) {
            const int n = idx >> 8, k = idx & 255;
            hsA[0][n][k] = __float2half_rn(h0all[(size_t)(b0 + n) * HD + k]);
        }
        __syncthreads();

        const size_t fb = (((size_t)cid * 2 + crank) * 8 + w) * 128 + lane * 4;
        float4 xc = *(const float4*)(g_Xp0 + fb);
        int ph0 = 0, ph1 = 0;

        for (int u = 0; u <= TLEN; ++u) {
            const int rd = u & 1, wr = rd ^ 1;

            float c[4] = {}, c2[4] = {};
            if (u < TLEN) MMA_STEP16(c, c2, afr, lsm0 + rd * BUFB);

            // publish h0(u-1), own half only (coalesced, behind MMA drain)
            if (u > 0 && tid < 128) {
                const int pn = tid >> 4, pc = (tid & 15) * 8;
                uint4 v = *(const uint4*)&hsA[rd][pn][crank * 128 + pc];
                *(uint4*)((char*)g_H0h + ((((size_t)(u - 1) * 4 + cid) * 8 + pn) * 512)
                          + (crank * 128 + pc) * 2) = v;
            }

            if (u < TLEN) {
                const int tn = (u + 1 < TLEN) ? u + 1 : TLEN - 1;
                float4 xn = *(const float4*)(g_Xp0 + (size_t)tn * 8192 + fb);

                const float* x = (const float*)&xc;
                float v0 = tanh_mufu(c[0] + c2[0] + x[0]);
                float v1 = tanh_mufu(c[1] + c2[1] + x[1]);
                float v2 = tanh_mufu(c[2] + c2[2] + x[2]);
                float v3 = tanh_mufu(c[3] + c2[3] + x[3]);
                __half h0_ = __float2half_rn(v0), h1_ = __float2half_rn(v1);
                __half h2_ = __float2half_rn(v2), h3_ = __float2half_rn(v3);
                hsA[wr][n0][hbase]         = h0_;
                hsA[wr][n0 + 1][hbase]     = h1_;
                hsA[wr][n0][hbase + 8]     = h2_;
                hsA[wr][n0 + 1][hbase + 8] = h3_;
                const uint32_t rb = rbase + wr * BUFB;
                st_cluster16(rb + (n0 * HS + hbase) * 2,           h0_);
                st_cluster16(rb + ((n0 + 1) * HS + hbase) * 2,     h1_);
                st_cluster16(rb + (n0 * HS + hbase + 8) * 2,       h2_);
                st_cluster16(rb + ((n0 + 1) * HS + hbase + 8) * 2, h3_);
                xc = xn;
            }
            __syncthreads();
            if (u < TLEN) {
                if (tid == 0) mbar_arrive_peer(mb_peer0 + wr * 8);
                mbar_wait(mb0 + wr * 8, wr ? ph1 : ph0);
                if (wr) ph1 ^= 1; else ph0 ^= 1;
            }
            if (tid == 0 && u > 0 && ((u & 3) == 0 || u == TLEN))
                st_rel(&g_progA[cid * 2 + crank], u);
        }
    }
    // ======================= Stage B: xp1 projection ========================
    else if (role == 1) {
        uint32_t afr[16][4];
        load_frags16(afr, Wih1, hbase, tid4);
        const float bias_lo = b_ih[HD + hbase] + b_hh[HD + hbase];
        const float bias_hi = b_ih[HD + hbase + 8] + b_hh[HD + hbase + 8];

        const int ln = tid >> 5, kb = (tid & 31) * 8;

        int avA = 0;
        if (tid == 0) {
            while (true) {
                int a0 = ld_acq(&g_progA[cid * 2]);
                int a1 = ld_acq(&g_progA[cid * 2 + 1]);
                avA = a0 < a1 ? a0 : a1;
                if (avA >= 32) break;
                __nanosleep(200);
            }
        }

        for (int tp = 0; tp < TLEN; tp += 2) {
            if (tid == 0 && avA < tp + 2) {
                do {
                    int a0 = ld_acq(&g_progA[cid * 2]);
                    int a1 = ld_acq(&g_progA[cid * 2 + 1]);
                    avA = a0 < a1 ? a0 : a1;
                } while (avA < tp + 2);
            }
            __syncthreads();

            uint4 v0 = *(const uint4*)((const char*)g_H0h +
                        ((((size_t)tp * 4 + cid) * 8 + ln) * 512) + kb * 2);
            uint4 v1 = *(const uint4*)((const char*)g_H0h +
                        ((((size_t)(tp + 1) * 4 + cid) * 8 + ln) * 512) + kb * 2);
            *(uint4*)&hsA[0][ln][kb] = v0;
            *(uint4*)&hsA[1][ln][kb] = v1;
            __syncthreads();

            #pragma unroll
            for (int s = 0; s < 2; ++s) {
                float c[4] = {}, c2[4] = {};
                MMA_STEP16(c, c2, afr, lsm0 + s * BUFB);
                float4 o;
                o.x = c[0] + c2[0] + bias_lo;
                o.y = c[1] + c2[1] + bias_lo;
                o.z = c[2] + c2[2] + bias_hi;
                o.w = c[3] + c2[3] + bias_hi;
                *(float4*)(g_Xp1 +
                    ((((size_t)(tp + s) * 4 + cid) * 2 + crank) * 8 + w) * 128 + lane * 4) = o;
            }
            __syncthreads();
            if (tid == 0 && (((tp + 2) & 7) == 0 || tp + 2 == TLEN))
                st_rel(&g_progB[cid * 2 + crank], tp + 2);
        }
    }
    // ======================= Stage C: layer-1 recurrence ====================
    else {
        uint32_t afr[16][4];
        load_frags16(afr, Whh1, hbase, tid4);

        const float* h0l1 = h0all + (size_t)NB * HD;
        for (int idx = tid; idx < 8 * HD; idx += 256) {
            const int n = idx >> 8, k = idx & 255;
            hsA[0][n][k] = __float2half_rn(h0l1[(size_t)(b0 + n) * HD + k]);
        }
        __syncthreads();

        int avB = 0;
        while (true) {
            int a0 = ld_acq(&g_progB[cid * 2]);
            int a1 = ld_acq(&g_progB[cid * 2 + 1]);
            avB = a0 < a1 ? a0 : a1;
            if (avB >= 64) break;
            __nanosleep(200);
        }

        const size_t fb = (((size_t)cid * 2 + crank) * 8 + w) * 128 + lane * 4;
        float4 xc = *(const float4*)(g_Xp1 + fb);
        int ph0 = 0, ph1 = 0;

        for (int u = 0; u <= TLEN; ++u) {
            const int rd = u & 1, wr = rd ^ 1;

            float c[4] = {}, c2[4] = {};
            if (u < TLEN) MMA_STEP16(c, c2, afr, lsm0 + rd * BUFB);

            // flush Out(u-1), own half (behind MMA drain)
            if (u > 0) {
                const int fn = tid >> 5, fc = (tid & 31) * 4;
                float4 a = *(const float4*)&obuf[rd][fn][fc];
                *(float4*)(Out + ((size_t)(u - 1) * NB + b0 + fn) * HD
                           + crank * 128 + fc) = a;
            }

            if (u < TLEN) {
                const int tn = (u + 1 < TLEN) ? u + 1 : TLEN - 1;
                if (avB < tn + 1) {
                    do {
                        int a0 = ld_acq(&g_progB[cid * 2]);
                        int a1 = ld_acq(&g_progB[cid * 2 + 1]);
                        avB = a0 < a1 ? a0 : a1;
                    } while (avB < tn + 1);
                }
                float4 xn = *(const float4*)(g_Xp1 + (size_t)tn * 8192 + fb);

                const float* x = (const float*)&xc;
                float v0 = tanh_mufu(c[0] + c2[0] + x[0]);
                float v1 = tanh_mufu(c[1] + c2[1] + x[1]);
                float v2 = tanh_mufu(c[2] + c2[2] + x[2]);
                float v3 = tanh_mufu(c[3] + c2[3] + x[3]);
                __half h0_ = __float2half_rn(v0), h1_ = __float2half_rn(v1);
                __half h2_ = __float2half_rn(v2), h3_ = __float2half_rn(v3);
                hsA[wr][n0][hbase]         = h0_;
                hsA[wr][n0 + 1][hbase]     = h1_;
                hsA[wr][n0][hbase + 8]     = h2_;
                hsA[wr][n0 + 1][hbase + 8] = h3_;
                const uint32_t rb = rbase + wr * BUFB;
                st_cluster16(rb + (n0 * HS + hbase) * 2,           h0_);
                st_cluster16(rb + ((n0 + 1) * HS + hbase) * 2,     h1_);
                st_cluster16(rb + (n0 * HS + hbase + 8) * 2,       h2_);
                st_cluster16(rb + ((n0 + 1) * HS + hbase + 8) * 2, h3_);
                obuf[wr][n0][hloc]         = v0;
                obuf[wr][n0 + 1][hloc]     = v1;
                obuf[wr][n0][hloc + 8]     = v2;
                obuf[wr][n0 + 1][hloc + 8] = v3;
                xc = xn;
            }
            __syncthreads();
            if (u < TLEN) {
                if (tid == 0) mbar_arrive_peer(mb_peer0 + wr * 8);
                mbar_wait(mb0 + wr * 8, wr ? ph1 : ph0);
                if (wr) ph1 ^= 1; else ph0 ^= 1;
            }
        }
    }
}

// --------------------------- input-path GEMM (layer 0) ----------------------
// Xp0 = x @ W_ih0^T + biases, stored in the cluster frag layout.
#define BM 64
#define BN 64
#define BK 16

__global__ void __launch_bounds__(256) gemm_xw_kernel(
    const float* __restrict__ In, const float* __restrict__ W,
    const float* __restrict__ bi, const float* __restrict__ bh,
    float* __restrict__ OutF)
{
    __shared__ float As[BM][BK + 1];
    __shared__ float Bs[BN][BK + 1];

    const int row0 = blockIdx.y * BM;
    const int col0 = blockIdx.x * BN;
    const int tid  = threadIdx.x;

    if (blockIdx.x == 0 && blockIdx.y == 0 && tid == 0) {
        #pragma unroll
        for (int i = 0; i < 8; ++i) { g_progA[i] = 0; g_progB[i] = 0; }
    }

    const int tx = tid & 15;
    const int ty = tid >> 4;

    float acc[4][4] = {};

    const int lr = tid >> 2;
    const int lc = (tid & 3) << 2;

    for (int k0 = 0; k0 < HD; k0 += BK) {
        float4 a = *(const float4*)&In[(size_t)(row0 + lr) * HD + k0 + lc];
        float4 b = *(const float4*)&W [(size_t)(col0 + lr) * HD + k0 + lc];
        As[lr][lc] = a.x; As[lr][lc + 1] = a.y; As[lr][lc + 2] = a.z; As[lr][lc + 3] = a.w;
        Bs[lr][lc] = b.x; Bs[lr][lc + 1] = b.y; Bs[lr][lc + 2] = b.z; Bs[lr][lc + 3] = b.w;
        __syncthreads();
        #pragma unroll
        for (int kk = 0; kk < BK; ++kk) {
            float av[4], bv[4];
            #pragma unroll
            for (int i = 0; i < 4; ++i) av[i] = As[ty * 4 + i][kk];
            #pragma unroll
            for (int j = 0; j < 4; ++j) bv[j] = Bs[tx * 4 + j][kk];
            #pragma unroll
            for (int i = 0; i < 4; ++i)
                #pragma unroll
                for (int j = 0; j < 4; ++j) acc[i][j] += av[i] * bv[j];
        }
        __syncthreads();
    }

    #pragma unroll
    for (int j = 0; j < 4; ++j) {
        const int h = col0 + tx * 4 + j;
        const float bias = bi[h] + bh[h];
        const int rank = h >> 7, wA = (h >> 4) & 7, grpA = h & 7, ihi = (h >> 3) & 1;
        #pragma unroll
        for (int i = 0; i < 4; ++i) {
            const int r = row0 + ty * 4 + i;
            const int t = r >> 5, b = r & 31;
            const int g = b >> 3, n = b & 7;
            const int laneA = grpA * 4 + (n >> 1);
            OutF[((((size_t)t * 4 + g) * 2 + rank) * 8 + wA) * 128
                 + laneA * 4 + ihi * 2 + (n & 1)] = acc[i][j] + bias;
        }
    }
}

// -------------------------------- launcher ----------------------------------
extern "C" void kernel_launch(void* const* d_in, const int* in_sizes, int n_in,
                              void* d_out, int out_size) {
    const float* x    = (const float*)d_in[0];  // [T,B,D]
    const float* W_ih = (const float*)d_in[1];  // [L,H,D]
    const float* W_hh = (const float*)d_in[2];  // [L,H,H]
    const float* b_ih = (const float*)d_in[3];  // [L,H]
    const float* b_hh = (const float*)d_in[4];  // [L,H]
    const float* h0   = (const float*)d_in[5];  // [L,B,H]
    float* out = (float*)d_out;                 // [T,B,H]

    float* Xp0 = nullptr;
    cudaGetSymbolAddress((void**)&Xp0, g_Xp0);

    const dim3 gemm_grid(HD / BN, (TLEN * NB) / BM);

    gemm_xw_kernel<<<gemm_grid, 256>>>(x, W_ih, b_ih, b_hh, Xp0);
    rnn_fused_kernel<<<24, 256>>>(W_hh, W_hh + HD * HD, W_ih + HD * HD,
                                  b_ih, b_hh, h0, out);
}

// round 9
// speedup vs baseline: 1.2641x; 1.2641x over previous
#include <cuda_runtime.h>
#include <cuda_fp16.h>
#include <cstdint>
#include <cstddef>

#define TLEN 4096
#define NB   32
#define HD   256
#define HS   264   // smem halves per n-row (256 + 8 pad)

// Scratch (device globals: allocation-free rule)
static __device__ __align__(256) float  g_Xp0[(size_t)TLEN * NB * HD]; // frag-layout preacts L0
static __device__ __align__(256) float  g_Xp1[(size_t)TLEN * NB * HD]; // frag-layout preacts L1
static __device__ __align__(256) __half g_H0h[(size_t)TLEN * NB * HD]; // L0 hidden [t][cid][n][256]
static __device__ int g_progA[4];
static __device__ int g_progB[4];

// ---------------------------------------------------------------------------
__device__ __forceinline__ float tanh_mufu(float x) {
    float y;
    asm("tanh.approx.f32 %0, %1;" : "=f"(y) : "f"(x));
    return y;
}
__device__ __forceinline__ uint32_t pack_h2(float lo, float hi) {
    __half2 h = __floats2half2_rn(lo, hi);
    return *reinterpret_cast<uint32_t*>(&h);
}
__device__ __forceinline__ uint32_t smem_u32(const void* p) {
    uint32_t a;
    asm("{ .reg .u64 t; cvta.to.shared.u64 t, %1; cvt.u32.u64 %0, t; }" : "=r"(a) : "l"(p));
    return a;
}
__device__ __forceinline__ int ld_acq(const int* p) {
    int v;
    asm volatile("ld.acquire.gpu.global.s32 %0, [%1];" : "=r"(v) : "l"(p));
    return v;
}
__device__ __forceinline__ void st_rel(int* p, int v) {
    asm volatile("st.release.gpu.global.s32 [%0], %1;" :: "l"(p), "r"(v));
}
__device__ __forceinline__ int prewait(const int* p, int v) {
    int a;
    while ((a = ld_acq(p)) < v) { __nanosleep(200); }
    return a;
}
#define HMMA(acc, af, bf0, bf1)                                               \
    asm volatile(                                                             \
        "mma.sync.aligned.m16n8k16.row.col.f32.f16.f16.f32 "                  \
        "{%0,%1,%2,%3}, {%4,%5,%6,%7}, {%8,%9}, {%0,%1,%2,%3};"               \
        : "+f"((acc)[0]), "+f"((acc)[1]), "+f"((acc)[2]), "+f"((acc)[3])      \
        : "r"((af)[0]), "r"((af)[1]), "r"((af)[2]), "r"((af)[3]),             \
          "r"(bf0), "r"(bf1))
#define LDSM4(r0, r1, r2, r3, a)                                              \
    asm volatile("ldmatrix.sync.aligned.m8n8.x4.shared.b16 {%0,%1,%2,%3}, [%4];" \
        : "=r"(r0), "=r"(r1), "=r"(r2), "=r"(r3) : "r"(a))

// One M=16 tile x full K=256: 8 LDSM4 + 16 HMMA (two 8-deep accum chains).
#define MMA_STEP16(c, c2, afr, ab)                                            \
    do {                                                                      \
        _Pragma("unroll")                                                     \
        for (int kk = 0; kk < 8; ++kk) {                                      \
            uint32_t b0, b1, b2, b3;                                          \
            LDSM4(b0, b1, b2, b3, (ab) + kk * 64);                            \
            HMMA((c),  (afr)[2 * kk],     b0, b1);                            \
            HMMA((c2), (afr)[2 * kk + 1], b2, b3);                            \
        }                                                                     \
    } while (0)

// Register-resident A fragments for rows (r0, r0+8) of a 256x256 fp32 weight.
__device__ __forceinline__ void load_frags16(uint32_t afr[16][4],
                                             const float* __restrict__ W,
                                             int r0, int tid4) {
    #pragma unroll
    for (int kt = 0; kt < 16; ++kt) {
        const int k0 = kt * 16 + tid4 * 2;
        const float* p0 = W + (size_t)r0 * HD + k0;
        const float* p1 = W + (size_t)(r0 + 8) * HD + k0;
        afr[kt][0] = pack_h2(p0[0], p0[1]);
        afr[kt][1] = pack_h2(p1[0], p1[1]);
        afr[kt][2] = pack_h2(p0[8], p0[9]);
        afr[kt][3] = pack_h2(p1[8], p1[9]);
    }
}

// ---------------------------------------------------------------------------
// Fused 3-stage pipelined kernel.  grid = 12 CTAs x 512 threads (16 warps):
//   CTA 0-3  (A): layer-0 recurrence   CTA 4-7 (B): xp1 projection
//   CTA 8-11 (C): layer-1 recurrence
// Warp w owns M-tile rows [16w, 16w+16); afr = 64 regs/thread (no spills).
__global__ void __launch_bounds__(512, 1) rnn_fused_kernel(
    const float* __restrict__ Whh0, const float* __restrict__ Whh1,
    const float* __restrict__ Wih1,
    const float* __restrict__ b_ih, const float* __restrict__ b_hh,
    const float* __restrict__ h0all, float* __restrict__ Out)
{
    __shared__ __align__(16) __half hsA[2][8][HS];   // h state (dbl-buf) / B staging
    __shared__ __align__(16) float  obuf[2][8][264]; // C only: output staging

    const int tid  = threadIdx.x;
    const int w    = tid >> 5;        // warp 0..15 -> M rows [16w,16w+16)
    const int lane = tid & 31;
    const int grp  = lane >> 2;
    const int tid4 = lane & 3;
    const int role = blockIdx.x >> 2;   // 0=A, 1=B, 2=C
    const int cid  = blockIdx.x & 3;
    const int b0   = cid * 8;
    const int m0   = w * 16 + grp;      // output row (second row = +8)
    const int n0   = tid4 * 2;

    // ldmatrix lane address base (buffer 0)
    const uint32_t hs_base = smem_u32(&hsA[0][0][0]);
    const uint32_t lsm0 = hs_base + (uint32_t)(lane & 7) * (HS * 2) + (uint32_t)(lane >> 3) * 16;
    const uint32_t BUFB = 8 * HS * 2;   // bytes per h buffer

    // ======================= Stage A: layer-0 recurrence ====================
    if (role == 0) {
        uint32_t afr[16][4];
        load_frags16(afr, Whh0, m0, tid4);

        for (int idx = tid; idx < 8 * HD; idx += 512) {
            const int n = idx >> 8, k = idx & 255;
            hsA[0][n][k] = __float2half_rn(h0all[(size_t)(b0 + n) * HD + k]);
        }
        __syncthreads();

        const size_t fb = ((size_t)cid * 16 + w) * 128 + lane * 4;
        float4 xc = *(const float4*)(g_Xp0 + fb);

        for (int u = 0; u <= TLEN; ++u) {
            const int rd = u & 1, wr = rd ^ 1;

            float c[4] = {}, c2[4] = {};
            if (u < TLEN) MMA_STEP16(c, c2, afr, lsm0 + rd * BUFB);

            // publish h0(u-1) behind the MMA drain (coalesced uint2 per thread)
            if (u > 0) {
                const int n = tid >> 6, kb = (tid & 63) * 4;
                uint2 v = *(const uint2*)&hsA[rd][n][kb];
                *(uint2*)((char*)g_H0h +
                          ((((size_t)(u - 1) * 4 + cid) * 8 + n) * 512) + kb * 2) = v;
            }

            if (u < TLEN) {
                const int tn = (u + 1 < TLEN) ? u + 1 : TLEN - 1;
                float4 xn = *(const float4*)(g_Xp0 + (size_t)tn * 8192 + fb);

                const float* x = (const float*)&xc;
                float v0 = tanh_mufu(c[0] + c2[0] + x[0]);   // (m0,   n0)
                float v1 = tanh_mufu(c[1] + c2[1] + x[1]);   // (m0,   n0+1)
                float v2 = tanh_mufu(c[2] + c2[2] + x[2]);   // (m0+8, n0)
                float v3 = tanh_mufu(c[3] + c2[3] + x[3]);   // (m0+8, n0+1)
                hsA[wr][n0][m0]         = __float2half_rn(v0);
                hsA[wr][n0 + 1][m0]     = __float2half_rn(v1);
                hsA[wr][n0][m0 + 8]     = __float2half_rn(v2);
                hsA[wr][n0 + 1][m0 + 8] = __float2half_rn(v3);
                xc = xn;
            }
            __syncthreads();
            if (tid == 0 && u > 0 && ((u & 3) == 0 || u == TLEN))
                st_rel(&g_progA[cid], u);
        }
    }
    // ======================= Stage B: xp1 projection ========================
    else if (role == 1) {
        uint32_t afr[16][4];
        load_frags16(afr, Wih1, m0, tid4);
        const float bias_lo = b_ih[HD + m0] + b_hh[HD + m0];
        const float bias_hi = b_ih[HD + m0 + 8] + b_hh[HD + m0 + 8];

        const int ln = tid >> 6, kb = (tid & 63) * 4;

        int avA = 0;
        if (tid == 0) avA = prewait(&g_progA[cid], 32);

        for (int tp = 0; tp < TLEN; tp += 2) {
            if (tid == 0 && avA < tp + 2) {
                while ((avA = ld_acq(&g_progA[cid])) < tp + 2) {}
            }
            __syncthreads();

            uint2 v0 = *(const uint2*)((const char*)g_H0h +
                        ((((size_t)tp * 4 + cid) * 8 + ln) * 512) + kb * 2);
            uint2 v1 = *(const uint2*)((const char*)g_H0h +
                        ((((size_t)(tp + 1) * 4 + cid) * 8 + ln) * 512) + kb * 2);
            *(uint2*)&hsA[0][ln][kb] = v0;
            *(uint2*)&hsA[1][ln][kb] = v1;
            __syncthreads();

            #pragma unroll
            for (int s = 0; s < 2; ++s) {
                float c[4] = {}, c2[4] = {};
                MMA_STEP16(c, c2, afr, lsm0 + s * BUFB);
                float4 o;
                o.x = c[0] + c2[0] + bias_lo;
                o.y = c[1] + c2[1] + bias_lo;
                o.z = c[2] + c2[2] + bias_hi;
                o.w = c[3] + c2[3] + bias_hi;
                *(float4*)(g_Xp1 +
                    (((size_t)(tp + s) * 4 + cid) * 16 + w) * 128 + lane * 4) = o;
            }
            __syncthreads();
            if (tid == 0 && (((tp + 2) & 7) == 0 || tp + 2 == TLEN))
                st_rel(&g_progB[cid], tp + 2);
        }
    }
    // ======================= Stage C: layer-1 recurrence ====================
    else {
        uint32_t afr[16][4];
        load_frags16(afr, Whh1, m0, tid4);

        const float* h0l1 = h0all + (size_t)NB * HD;
        for (int idx = tid; idx < 8 * HD; idx += 512) {
            const int n = idx >> 8, k = idx & 255;
            hsA[0][n][k] = __float2half_rn(h0l1[(size_t)(b0 + n) * HD + k]);
        }
        __syncthreads();

        int avB = prewait(&g_progB[cid], 64);
        const size_t fb = ((size_t)cid * 16 + w) * 128 + lane * 4;
        float4 xc = *(const float4*)(g_Xp1 + fb);

        for (int u = 0; u <= TLEN; ++u) {
            const int rd = u & 1, wr = rd ^ 1;

            float c[4] = {}, c2[4] = {};
            if (u < TLEN) MMA_STEP16(c, c2, afr, lsm0 + rd * BUFB);

            // flush Out(u-1) behind the MMA drain (float4 per thread)
            if (u > 0) {
                const int fn = tid >> 6, fc = (tid & 63) * 4;
                float4 a = *(const float4*)&obuf[rd][fn][fc];
                *(float4*)(Out + ((size_t)(u - 1) * NB + b0 + fn) * HD + fc) = a;
            }

            if (u < TLEN) {
                const int tn = (u + 1 < TLEN) ? u + 1 : TLEN - 1;
                if (avB < tn + 1) {
                    while ((avB = ld_acq(&g_progB[cid])) < tn + 1) {}
                }
                float4 xn = *(const float4*)(g_Xp1 + (size_t)tn * 8192 + fb);

                const float* x = (const float*)&xc;
                float v0 = tanh_mufu(c[0] + c2[0] + x[0]);
                float v1 = tanh_mufu(c[1] + c2[1] + x[1]);
                float v2 = tanh_mufu(c[2] + c2[2] + x[2]);
                float v3 = tanh_mufu(c[3] + c2[3] + x[3]);
                hsA[wr][n0][m0]         = __float2half_rn(v0);
                hsA[wr][n0 + 1][m0]     = __float2half_rn(v1);
                hsA[wr][n0][m0 + 8]     = __float2half_rn(v2);
                hsA[wr][n0 + 1][m0 + 8] = __float2half_rn(v3);
                obuf[wr][n0][m0]         = v0;
                obuf[wr][n0 + 1][m0]     = v1;
                obuf[wr][n0][m0 + 8]     = v2;
                obuf[wr][n0 + 1][m0 + 8] = v3;
                xc = xn;
            }
            __syncthreads();
        }
    }
}

// --------------------------- input-path GEMM (layer 0) ----------------------
// Xp0 = x @ W_ih0^T + biases, stored in the 16-warp frag layout.
#define BM 64
#define BN 64
#define BK 16

__global__ void __launch_bounds__(256) gemm_xw_kernel(
    const float* __restrict__ In, const float* __restrict__ W,
    const float* __restrict__ bi, const float* __restrict__ bh,
    float* __restrict__ OutF)
{
    __shared__ float As[BM][BK + 1];
    __shared__ float Bs[BN][BK + 1];

    const int row0 = blockIdx.y * BM;
    const int col0 = blockIdx.x * BN;
    const int tid  = threadIdx.x;

    if (blockIdx.x == 0 && blockIdx.y == 0 && tid == 0) {
        #pragma unroll
        for (int i = 0; i < 4; ++i) { g_progA[i] = 0; g_progB[i] = 0; }
    }

    const int tx = tid & 15;
    const int ty = tid >> 4;

    float acc[4][4] = {};

    const int lr = tid >> 2;
    const int lc = (tid & 3) << 2;

    for (int k0 = 0; k0 < HD; k0 += BK) {
        float4 a = *(const float4*)&In[(size_t)(row0 + lr) * HD + k0 + lc];
        float4 b = *(const float4*)&W [(size_t)(col0 + lr) * HD + k0 + lc];
        As[lr][lc] = a.x; As[lr][lc + 1] = a.y; As[lr][lc + 2] = a.z; As[lr][lc + 3] = a.w;
        Bs[lr][lc] = b.x; Bs[lr][lc + 1] = b.y; Bs[lr][lc + 2] = b.z; Bs[lr][lc + 3] = b.w;
        __syncthreads();
        #pragma unroll
        for (int kk = 0; kk < BK; ++kk) {
            float av[4], bv[4];
            #pragma unroll
            for (int i = 0; i < 4; ++i) av[i] = As[ty * 4 + i][kk];
            #pragma unroll
            for (int j = 0; j < 4; ++j) bv[j] = Bs[tx * 4 + j][kk];
            #pragma unroll
            for (int i = 0; i < 4; ++i)
                #pragma unroll
                for (int j = 0; j < 4; ++j) acc[i][j] += av[i] * bv[j];
        }
        __syncthreads();
    }

    #pragma unroll
    for (int j = 0; j < 4; ++j) {
        const int h = col0 + tx * 4 + j;
        const float bias = bi[h] + bh[h];
        const int wA = h >> 4, grpA = h & 7, ihi = (h >> 3) & 1;
        #pragma unroll
        for (int i = 0; i < 4; ++i) {
            const int r = row0 + ty * 4 + i;
            const int t = r >> 5, b = r & 31;
            const int g = b >> 3, n = b & 7;
            const int laneA = grpA * 4 + (n >> 1);
            const int jj = ihi * 2 + (n & 1);
            OutF[(((size_t)t * 4 + g) * 16 + wA) * 128 + laneA * 4 + jj] = acc[i][j] + bias;
        }
    }
}

// -------------------------------- launcher ----------------------------------
extern "C" void kernel_launch(void* const* d_in, const int* in_sizes, int n_in,
                              void* d_out, int out_size) {
    const float* x    = (const float*)d_in[0];  // [T,B,D]
    const float* W_ih = (const float*)d_in[1];  // [L,H,D]
    const float* W_hh = (const float*)d_in[2];  // [L,H,H]
    const float* b_ih = (const float*)d_in[3];  // [L,H]
    const float* b_hh = (const float*)d_in[4];  // [L,H]
    const float* h0   = (const float*)d_in[5];  // [L,B,H]
    float* out = (float*)d_out;                 // [T,B,H]

    float* Xp0 = nullptr;
    cudaGetSymbolAddress((void**)&Xp0, g_Xp0);

    const dim3 gemm_grid(HD / BN, (TLEN * NB) / BM);

    gemm_xw_kernel<<<gemm_grid, 256>>>(x, W_ih, b_ih, b_hh, Xp0);
    rnn_fused_kernel<<<12, 512>>>(W_hh, W_hh + HD * HD, W_ih + HD * HD,
                                  b_ih, b_hh, h0, out);
}

// round 10
// speedup vs baseline: 1.6086x; 1.2726x over previous
#include <cuda_runtime.h>
#include <cuda_fp16.h>
#include <cstdint>
#include <cstddef>

#define TLEN 4096
#define NB   32
#define HD   256
#define HS   264   // smem halves per n-row (256 + 8 pad)

// Scratch (device globals: allocation-free rule)
static __device__ __align__(256) float  g_Xp0[(size_t)TLEN * NB * HD]; // frag-layout preacts L0
static __device__ __align__(256) float  g_Xp1[(size_t)TLEN * NB * HD]; // frag-layout preacts L1
static __device__ __align__(256) __half g_H0h[(size_t)TLEN * NB * HD]; // L0 hidden [t][cid][n][256]
static __device__ int g_progA[4];
static __device__ int g_progB[4];

// ---------------------------------------------------------------------------
__device__ __forceinline__ float tanh_mufu(float x) {
    float y;
    asm("tanh.approx.f32 %0, %1;" : "=f"(y) : "f"(x));
    return y;
}
__device__ __forceinline__ uint32_t pack_h2(float lo, float hi) {
    __half2 h = __floats2half2_rn(lo, hi);
    return *reinterpret_cast<uint32_t*>(&h);
}
__device__ __forceinline__ uint32_t smem_u32(const void* p) {
    uint32_t a;
    asm("{ .reg .u64 t; cvta.to.shared.u64 t, %1; cvt.u32.u64 %0, t; }" : "=r"(a) : "l"(p));
    return a;
}
__device__ __forceinline__ int ld_acq(const int* p) {
    int v;
    asm volatile("ld.acquire.gpu.global.s32 %0, [%1];" : "=r"(v) : "l"(p));
    return v;
}
__device__ __forceinline__ void st_rel(int* p, int v) {
    asm volatile("st.release.gpu.global.s32 [%0], %1;" :: "l"(p), "r"(v));
}
__device__ __forceinline__ int prewait(const int* p, int v) {
    int a;
    while ((a = ld_acq(p)) < v) { __nanosleep(200); }
    return a;
}
#define HMMA(acc, af, bf0, bf1)                                               \
    asm volatile(                                                             \
        "mma.sync.aligned.m16n8k16.row.col.f32.f16.f16.f32 "                  \
        "{%0,%1,%2,%3}, {%4,%5,%6,%7}, {%8,%9}, {%0,%1,%2,%3};"               \
        : "+f"((acc)[0]), "+f"((acc)[1]), "+f"((acc)[2]), "+f"((acc)[3])      \
        : "r"((af)[0]), "r"((af)[1]), "r"((af)[2]), "r"((af)[3]),             \
          "r"(bf0), "r"(bf1))
#define LDSM4(r0, r1, r2, r3, a)                                              \
    asm volatile("ldmatrix.sync.aligned.m8n8.x4.shared.b16 {%0,%1,%2,%3}, [%4];" \
        : "=r"(r0), "=r"(r1), "=r"(r2), "=r"(r3) : "r"(a))

// One M=16 tile x full K=256: 8 LDSM4 + 16 HMMA across FOUR depth-4 chains.
#define MMA_STEP16(c0, c1, c2, c3, afr, ab)                                   \
    do {                                                                      \
        _Pragma("unroll")                                                     \
        for (int kk = 0; kk < 8; ++kk) {                                      \
            uint32_t b0, b1, b2, b3;                                          \
            LDSM4(b0, b1, b2, b3, (ab) + kk * 64);                            \
            if (kk < 4) {                                                     \
                HMMA((c0), (afr)[2 * kk],     b0, b1);                        \
                HMMA((c1), (afr)[2 * kk + 1], b2, b3);                        \
            } else {                                                          \
                HMMA((c2), (afr)[2 * kk],     b0, b1);                        \
                HMMA((c3), (afr)[2 * kk + 1], b2, b3);                        \
            }                                                                 \
        }                                                                     \
    } while (0)

#define SUM4(i) (((c0)[i] + (c2)[i]) + ((c1)[i] + (c3)[i]))

// Register-resident A fragments for rows (r0, r0+8) of a 256x256 fp32 weight.
__device__ __forceinline__ void load_frags16(uint32_t afr[16][4],
                                             const float* __restrict__ W,
                                             int r0, int tid4) {
    #pragma unroll
    for (int kt = 0; kt < 16; ++kt) {
        const int k0 = kt * 16 + tid4 * 2;
        const float* p0 = W + (size_t)r0 * HD + k0;
        const float* p1 = W + (size_t)(r0 + 8) * HD + k0;
        afr[kt][0] = pack_h2(p0[0], p0[1]);
        afr[kt][1] = pack_h2(p1[0], p1[1]);
        afr[kt][2] = pack_h2(p0[8], p0[9]);
        afr[kt][3] = pack_h2(p1[8], p1[9]);
    }
}

// ---------------------------------------------------------------------------
// Fused 3-stage pipelined kernel.  grid = 12 CTAs x 512 threads (16 warps):
//   CTA 0-3 (A): layer-0 recurrence   CTA 4-7 (B): xp1 projection
//   CTA 8-11 (C): layer-1 recurrence
__global__ void __launch_bounds__(512, 1) rnn_fused_kernel(
    const float* __restrict__ Whh0, const float* __restrict__ Whh1,
    const float* __restrict__ Wih1,
    const float* __restrict__ b_ih, const float* __restrict__ b_hh,
    const float* __restrict__ h0all, float* __restrict__ Out)
{
    __shared__ __align__(16) __half hsA[2][8][HS];   // h state (dbl-buf) / B staging
    __shared__ __align__(16) float  obuf[2][8][264]; // C only: output staging

    const int tid  = threadIdx.x;
    const int w    = tid >> 5;        // warp 0..15 -> M rows [16w,16w+16)
    const int lane = tid & 31;
    const int grp  = lane >> 2;
    const int tid4 = lane & 3;
    const int role = blockIdx.x >> 2;   // 0=A, 1=B, 2=C
    const int cid  = blockIdx.x & 3;
    const int b0   = cid * 8;
    const int m0   = w * 16 + grp;      // output row (second row = +8)
    const int n0   = tid4 * 2;

    const uint32_t hs_base = smem_u32(&hsA[0][0][0]);
    const uint32_t lsm0 = hs_base + (uint32_t)(lane & 7) * (HS * 2) + (uint32_t)(lane >> 3) * 16;
    const uint32_t BUFB = 8 * HS * 2;   // bytes per h buffer

    // ======================= Stage A: layer-0 recurrence ====================
    if (role == 0) {
        uint32_t afr[16][4];
        load_frags16(afr, Whh0, m0, tid4);

        for (int idx = tid; idx < 8 * HD; idx += 512) {
            const int n = idx >> 8, k = idx & 255;
            hsA[0][n][k] = __float2half_rn(h0all[(size_t)(b0 + n) * HD + k]);
        }
        __syncthreads();

        const size_t fb = ((size_t)cid * 16 + w) * 128 + lane * 4;
        float4 xa = *(const float4*)(g_Xp0 + fb);           // x(0)
        float4 xb = *(const float4*)(g_Xp0 + 8192 + fb);    // x(1)

        for (int u = 0; u <= TLEN; ++u) {
            const int rd = u & 1, wr = rd ^ 1;

            float c0[4] = {}, c1[4] = {}, c2[4] = {}, c3[4] = {};
            if (u < TLEN) MMA_STEP16(c0, c1, c2, c3, afr, lsm0 + rd * BUFB);

            // publish h0(u-1) behind the MMA drain (coalesced uint2 per thread)
            if (u > 0) {
                const int n = tid >> 6, kb = (tid & 63) * 4;
                uint2 v = *(const uint2*)&hsA[rd][n][kb];
                *(uint2*)((char*)g_H0h +
                          ((((size_t)(u - 1) * 4 + cid) * 8 + n) * 512) + kb * 2) = v;
            }

            if (u < TLEN) {
                const int tn = (u + 2 < TLEN) ? u + 2 : TLEN - 1;
                float4 xn = *(const float4*)(g_Xp0 + (size_t)tn * 8192 + fb);

                const float* x = (const float*)&xa;
                float v0 = tanh_mufu(SUM4(0) + x[0]);   // (m0,   n0)
                float v1 = tanh_mufu(SUM4(1) + x[1]);   // (m0,   n0+1)
                float v2 = tanh_mufu(SUM4(2) + x[2]);   // (m0+8, n0)
                float v3 = tanh_mufu(SUM4(3) + x[3]);   // (m0+8, n0+1)
                hsA[wr][n0][m0]         = __float2half_rn(v0);
                hsA[wr][n0 + 1][m0]     = __float2half_rn(v1);
                hsA[wr][n0][m0 + 8]     = __float2half_rn(v2);
                hsA[wr][n0 + 1][m0 + 8] = __float2half_rn(v3);
                xa = xb; xb = xn;
            }
            __syncthreads();
            if (tid == 0 && u > 0 && ((u & 3) == 0 || u == TLEN))
                st_rel(&g_progA[cid], u);
        }
    }
    // ======================= Stage B: xp1 projection ========================
    else if (role == 1) {
        uint32_t afr[16][4];
        load_frags16(afr, Wih1, m0, tid4);
        const float bias_lo = b_ih[HD + m0] + b_hh[HD + m0];
        const float bias_hi = b_ih[HD + m0 + 8] + b_hh[HD + m0 + 8];

        const int ln = tid >> 6, kb = (tid & 63) * 4;

        int avA = 0;
        if (tid == 0) avA = prewait(&g_progA[cid], 32);

        for (int tp = 0; tp < TLEN; tp += 2) {
            if (tid == 0 && avA < tp + 2) {
                while ((avA = ld_acq(&g_progA[cid])) < tp + 2) {}
            }
            __syncthreads();

            uint2 v0 = *(const uint2*)((const char*)g_H0h +
                        ((((size_t)tp * 4 + cid) * 8 + ln) * 512) + kb * 2);
            uint2 v1 = *(const uint2*)((const char*)g_H0h +
                        ((((size_t)(tp + 1) * 4 + cid) * 8 + ln) * 512) + kb * 2);
            *(uint2*)&hsA[0][ln][kb] = v0;
            *(uint2*)&hsA[1][ln][kb] = v1;
            __syncthreads();

            #pragma unroll
            for (int s = 0; s < 2; ++s) {
                float c0[4] = {}, c1[4] = {}, c2[4] = {}, c3[4] = {};
                MMA_STEP16(c0, c1, c2, c3, afr, lsm0 + s * BUFB);
                float4 o;
                o.x = SUM4(0) + bias_lo;
                o.y = SUM4(1) + bias_lo;
                o.z = SUM4(2) + bias_hi;
                o.w = SUM4(3) + bias_hi;
                *(float4*)(g_Xp1 +
                    (((size_t)(tp + s) * 4 + cid) * 16 + w) * 128 + lane * 4) = o;
            }
            __syncthreads();
            if (tid == 0 && (((tp + 2) & 7) == 0 || tp + 2 == TLEN))
                st_rel(&g_progB[cid], tp + 2);
        }
    }
    // ======================= Stage C: layer-1 recurrence ====================
    else {
        uint32_t afr[16][4];
        load_frags16(afr, Whh1, m0, tid4);

        const float* h0l1 = h0all + (size_t)NB * HD;
        for (int idx = tid; idx < 8 * HD; idx += 512) {
            const int n = idx >> 8, k = idx & 255;
            hsA[0][n][k] = __float2half_rn(h0l1[(size_t)(b0 + n) * HD + k]);
        }
        __syncthreads();

        int avB = prewait(&g_progB[cid], 64);
        const size_t fb = ((size_t)cid * 16 + w) * 128 + lane * 4;
        float4 xa = *(const float4*)(g_Xp1 + fb);
        float4 xb = *(const float4*)(g_Xp1 + 8192 + fb);

        for (int u = 0; u <= TLEN; ++u) {
            const int rd = u & 1, wr = rd ^ 1;

            float c0[4] = {}, c1[4] = {}, c2[4] = {}, c3[4] = {};
            if (u < TLEN) MMA_STEP16(c0, c1, c2, c3, afr, lsm0 + rd * BUFB);

            // flush Out(u-1) behind the MMA drain (float4 per thread)
            if (u > 0) {
                const int fn = tid >> 6, fc = (tid & 63) * 4;
                float4 a = *(const float4*)&obuf[rd][fn][fc];
                *(float4*)(Out + ((size_t)(u - 1) * NB + b0 + fn) * HD + fc) = a;
            }

            if (u < TLEN) {
                const int tn = (u + 2 < TLEN) ? u + 2 : TLEN - 1;
                if (avB < tn + 1) {
                    while ((avB = ld_acq(&g_progB[cid])) < tn + 1) {}
                }
                float4 xn = *(const float4*)(g_Xp1 + (size_t)tn * 8192 + fb);

                const float* x = (const float*)&xa;
                float v0 = tanh_mufu(SUM4(0) + x[0]);
                float v1 = tanh_mufu(SUM4(1) + x[1]);
                float v2 = tanh_mufu(SUM4(2) + x[2]);
                float v3 = tanh_mufu(SUM4(3) + x[3]);
                hsA[wr][n0][m0]         = __float2half_rn(v0);
                hsA[wr][n0 + 1][m0]     = __float2half_rn(v1);
                hsA[wr][n0][m0 + 8]     = __float2half_rn(v2);
                hsA[wr][n0 + 1][m0 + 8] = __float2half_rn(v3);
                obuf[wr][n0][m0]         = v0;
                obuf[wr][n0 + 1][m0]     = v1;
                obuf[wr][n0][m0 + 8]     = v2;
                obuf[wr][n0 + 1][m0 + 8] = v3;
                xa = xb; xb = xn;
            }
            __syncthreads();
        }
    }
}

// --------------------- input-path GEMM (layer 0, HMMA) ----------------------
// Xp0 = x @ W_ih0^T + biases, fp16 tensor cores, frag-layout output.
// 128 CTAs x 512 threads; each CTA processes 128 tiles of 8 rows.
__global__ void __launch_bounds__(512, 1) gemm0_hmma_kernel(
    const float* __restrict__ x, const float* __restrict__ Wih0,
    const float* __restrict__ bi, const float* __restrict__ bh,
    float* __restrict__ OutF)
{
    __shared__ __align__(16) __half xs[8][HS];

    const int tid  = threadIdx.x;
    const int w    = tid >> 5;
    const int lane = tid & 31;
    const int grp  = lane >> 2;
    const int m0   = w * 16 + grp;

    if (blockIdx.x == 0 && tid == 0) {
        #pragma unroll
        for (int i = 0; i < 4; ++i) { g_progA[i] = 0; g_progB[i] = 0; }
    }

    uint32_t afr[16][4];
    load_frags16(afr, Wih0, m0, lane & 3);
    const float bias_lo = bi[m0] + bh[m0];
    const float bias_hi = bi[m0 + 8] + bh[m0 + 8];

    const uint32_t xs_base = smem_u32(&xs[0][0]);
    const uint32_t lsm = xs_base + (uint32_t)(lane & 7) * (HS * 2) + (uint32_t)(lane >> 3) * 16;

    const int tile0 = blockIdx.x * 128;   // 16384 tiles total / 128 CTAs
    for (int it = 0; it < 128; ++it) {
        const int tile = tile0 + it;      // = t*4 + g
        // stage 8 rows of x (fp32 -> fp16), coalesced LDG
        #pragma unroll
        for (int q = 0; q < 4; ++q) {
            const int idx = tid + q * 512;
            const int n = idx >> 8, k = idx & 255;
            xs[n][k] = __float2half_rn(x[(size_t)tile * 8 * HD + (size_t)n * HD + k]);
        }
        __syncthreads();

        float c0[4] = {}, c1[4] = {}, c2[4] = {}, c3[4] = {};
        MMA_STEP16(c0, c1, c2, c3, afr, lsm);

        float4 o;
        o.x = SUM4(0) + bias_lo;
        o.y = SUM4(1) + bias_lo;
        o.z = SUM4(2) + bias_hi;
        o.w = SUM4(3) + bias_hi;
        *(float4*)(OutF + ((size_t)tile * 16 + w) * 128 + lane * 4) = o;
        __syncthreads();
    }
}

// -------------------------------- launcher ----------------------------------
extern "C" void kernel_launch(void* const* d_in, const int* in_sizes, int n_in,
                              void* d_out, int out_size) {
    const float* x    = (const float*)d_in[0];  // [T,B,D]
    const float* W_ih = (const float*)d_in[1];  // [L,H,D]
    const float* W_hh = (const float*)d_in[2];  // [L,H,H]
    const float* b_ih = (const float*)d_in[3];  // [L,H]
    const float* b_hh = (const float*)d_in[4];  // [L,H]
    const float* h0   = (const float*)d_in[5];  // [L,B,H]
    float* out = (float*)d_out;                 // [T,B,H]

    float* Xp0 = nullptr;
    cudaGetSymbolAddress((void**)&Xp0, g_Xp0);

    gemm0_hmma_kernel<<<128, 512>>>(x, W_ih, b_ih, b_hh, Xp0);
    rnn_fused_kernel<<<12, 512>>>(W_hh, W_hh + HD * HD, W_ih + HD * HD,
                                  b_ih, b_hh, h0, out);
}

// round 12
// speedup vs baseline: 1.6999x; 1.0567x over previous
#include <cuda_runtime.h>
#include <cuda_fp16.h>
#include <cstdint>
#include <cstddef>

#define TLEN 4096
#define NB   32
#define HD   256
#define HS   264   // gemm0 staging: halves per n-row (256 + 8 pad)

// Scratch (device globals: allocation-free rule)
static __device__ __align__(256) float  g_Xp0[(size_t)TLEN * NB * HD]; // frag-layout preacts L0
static __device__ __align__(256) float  g_Xp1[(size_t)TLEN * NB * HD]; // frag-layout preacts L1
static __device__ __align__(256) __half g_H0h[(size_t)TLEN * NB * HD]; // L0 hidden [t][cid][k][n]
static __device__ int g_progA[4];
static __device__ int g_progB[4];

// ---------------------------------------------------------------------------
__device__ __forceinline__ float tanh_mufu(float x) {
    float y;
    asm("tanh.approx.f32 %0, %1;" : "=f"(y) : "f"(x));
    return y;
}
__device__ __forceinline__ uint32_t pack_h2(float lo, float hi) {
    __half2 h = __floats2half2_rn(lo, hi);
    return *reinterpret_cast<uint32_t*>(&h);
}
__device__ __forceinline__ uint32_t smem_u32(const void* p) {
    uint32_t a;
    asm("{ .reg .u64 t; cvta.to.shared.u64 t, %1; cvt.u32.u64 %0, t; }" : "=r"(a) : "l"(p));
    return a;
}
__device__ __forceinline__ int ld_acq(const int* p) {
    int v;
    asm volatile("ld.acquire.gpu.global.s32 %0, [%1];" : "=r"(v) : "l"(p));
    return v;
}
__device__ __forceinline__ void st_rel(int* p, int v) {
    asm volatile("st.release.gpu.global.s32 [%0], %1;" :: "l"(p), "r"(v));
}
__device__ __forceinline__ int prewait(const int* p, int v) {
    int a;
    while ((a = ld_acq(p)) < v) { __nanosleep(200); }
    return a;
}
#define HMMA(acc, af, bf0, bf1)                                               \
    asm volatile(                                                             \
        "mma.sync.aligned.m16n8k16.row.col.f32.f16.f16.f32 "                  \
        "{%0,%1,%2,%3}, {%4,%5,%6,%7}, {%8,%9}, {%0,%1,%2,%3};"               \
        : "+f"((acc)[0]), "+f"((acc)[1]), "+f"((acc)[2]), "+f"((acc)[3])      \
        : "r"((af)[0]), "r"((af)[1]), "r"((af)[2]), "r"((af)[3]),             \
          "r"(bf0), "r"(bf1))
#define LDSM4(r0, r1, r2, r3, a)                                              \
    asm volatile("ldmatrix.sync.aligned.m8n8.x4.shared.b16 {%0,%1,%2,%3}, [%4];" \
        : "=r"(r0), "=r"(r1), "=r"(r2), "=r"(r3) : "r"(a))
#define LDSM4T(r0, r1, r2, r3, a)                                             \
    asm volatile("ldmatrix.sync.aligned.m8n8.x4.trans.shared.b16 {%0,%1,%2,%3}, [%4];" \
        : "=r"(r0), "=r"(r1), "=r"(r2), "=r"(r3) : "r"(a))

// n-major (gemm0): 8 LDSM4 + 16 HMMA, four depth-4 chains.
#define MMA_STEP16(c0, c1, c2, c3, afr, ab)                                   \
    do {                                                                      \
        _Pragma("unroll")                                                     \
        for (int kk = 0; kk < 8; ++kk) {                                      \
            uint32_t b0, b1, b2, b3;                                          \
            LDSM4(b0, b1, b2, b3, (ab) + kk * 64);                            \
            if (kk < 4) {                                                     \
                HMMA((c0), (afr)[2 * kk],     b0, b1);                        \
                HMMA((c1), (afr)[2 * kk + 1], b2, b3);                        \
            } else {                                                          \
                HMMA((c2), (afr)[2 * kk],     b0, b1);                        \
                HMMA((c3), (afr)[2 * kk + 1], b2, b3);                        \
            }                                                                 \
        }                                                                     \
    } while (0)

// k-major (scan): 8 LDSM4T + 16 HMMA; kk covers 32 k-rows (512 B) each.
#define MMA_STEP16T(c0, c1, c2, c3, afr, ab)                                  \
    do {                                                                      \
        _Pragma("unroll")                                                     \
        for (int kk = 0; kk < 8; ++kk) {                                      \
            uint32_t b0, b1, b2, b3;                                          \
            LDSM4T(b0, b1, b2, b3, (ab) + kk * 512);                          \
            if (kk < 4) {                                                     \
                HMMA((c0), (afr)[2 * kk],     b0, b1);                        \
                HMMA((c1), (afr)[2 * kk + 1], b2, b3);                        \
            } else {                                                          \
                HMMA((c2), (afr)[2 * kk],     b0, b1);                        \
                HMMA((c3), (afr)[2 * kk + 1], b2, b3);                        \
            }                                                                 \
        }                                                                     \
    } while (0)

#define SUM4(i) (((c0)[i] + (c2)[i]) + ((c1)[i] + (c3)[i]))

// Register-resident A fragments for rows (r0, r0+8) of a 256x256 fp32 weight.
__device__ __forceinline__ void load_frags16(uint32_t afr[16][4],
                                             const float* __restrict__ W,
                                             int r0, int tid4) {
    #pragma unroll
    for (int kt = 0; kt < 16; ++kt) {
        const int k0 = kt * 16 + tid4 * 2;
        const float* p0 = W + (size_t)r0 * HD + k0;
        const float* p1 = W + (size_t)(r0 + 8) * HD + k0;
        afr[kt][0] = pack_h2(p0[0], p0[1]);
        afr[kt][1] = pack_h2(p1[0], p1[1]);
        afr[kt][2] = pack_h2(p0[8], p0[9]);
        afr[kt][3] = pack_h2(p1[8], p1[9]);
    }
}

// ---------------------------------------------------------------------------
// Fused 3-stage pipelined kernel.  grid = 12 CTAs x 512 threads (16 warps):
//   CTA 0-3 (A): layer-0 recurrence   CTA 4-7 (B): xp1 projection
//   CTA 8-11 (C): layer-1 recurrence
// h state: k-major hsT[buf][k][n] (8 halves/row, conflict-free for trans-LDSM
// and for the packed epilogue stores).
__global__ void __launch_bounds__(512, 1) rnn_fused_kernel(
    const float* __restrict__ Whh0, const float* __restrict__ Whh1,
    const float* __restrict__ Wih1,
    const float* __restrict__ b_ih, const float* __restrict__ b_hh,
    const float* __restrict__ h0all, float* __restrict__ Out)
{
    __shared__ __align__(16) __half hsT[2][256][8];  // 4 KB per buffer
    __shared__ __align__(16) float  obuf[2][8][260]; // C only: output staging

    const int tid  = threadIdx.x;
    const int w    = tid >> 5;        // warp 0..15 -> M rows [16w,16w+16)
    const int lane = tid & 31;
    const int grp  = lane >> 2;
    const int tid4 = lane & 3;
    const int role = blockIdx.x >> 2;   // 0=A, 1=B, 2=C
    const int cid  = blockIdx.x & 3;
    const int b0   = cid * 8;
    const int m0   = w * 16 + grp;      // output row (second row = +8)
    const int n0   = tid4 * 2;

    const uint32_t hs_base = smem_u32(&hsT[0][0][0]);
    const uint32_t lsmT = hs_base + (uint32_t)lane * 16;  // 32 consecutive k-rows
    const uint32_t BUFB = 4096;                            // bytes per h buffer

    // ======================= Stage A: layer-0 recurrence ====================
    if (role == 0) {
        uint32_t afr[16][4];
        load_frags16(afr, Whh0, m0, tid4);

        for (int idx = tid; idx < 2048; idx += 512) {
            const int k = idx >> 3, n = idx & 7;
            hsT[0][k][n] = __float2half_rn(h0all[(size_t)(b0 + n) * HD + k]);
        }
        __syncthreads();

        const size_t fb = ((size_t)cid * 16 + w) * 128 + lane * 4;
        float4 xa = *(const float4*)(g_Xp0 + fb);           // x(0)
        float4 xb = *(const float4*)(g_Xp0 + 8192 + fb);    // x(1)

        for (int u = 0; u <= TLEN; ++u) {
            const int rd = u & 1, wr = rd ^ 1;

            float c0[4] = {}, c1[4] = {}, c2[4] = {}, c3[4] = {};
            if (u < TLEN) MMA_STEP16T(c0, c1, c2, c3, afr, lsmT + rd * BUFB);

            // publish h0(u-1) behind the MMA drain (flat 4KB copy, uint2/thread)
            if (u > 0) {
                uint2 v = *(const uint2*)((const char*)&hsT[rd][0][0] + tid * 8);
                *(uint2*)((char*)g_H0h +
                          (((size_t)(u - 1) * 4 + cid) * 4096) + tid * 8) = v;
            }

            if (u < TLEN) {
                const int tn = (u + 2 < TLEN) ? u + 2 : TLEN - 1;
                float4 xn = *(const float4*)(g_Xp0 + (size_t)tn * 8192 + fb);

                const float* x = (const float*)&xa;
                float v0 = tanh_mufu(SUM4(0) + x[0]);   // (m0,   n0)
                float v1 = tanh_mufu(SUM4(1) + x[1]);   // (m0,   n0+1)
                float v2 = tanh_mufu(SUM4(2) + x[2]);   // (m0+8, n0)
                float v3 = tanh_mufu(SUM4(3) + x[3]);   // (m0+8, n0+1)
                *(uint32_t*)&hsT[wr][m0][n0]     = pack_h2(v0, v1);
                *(uint32_t*)&hsT[wr][m0 + 8][n0] = pack_h2(v2, v3);
                xa = xb; xb = xn;
            }
            __syncthreads();
            if (tid == 0 && u > 0 && ((u & 3) == 0 || u == TLEN))
                st_rel(&g_progA[cid], u);
        }
    }
    // ======================= Stage B: xp1 projection ========================
    else if (role == 1) {
        uint32_t afr[16][4];
        load_frags16(afr, Wih1, m0, tid4);
        const float bias_lo = b_ih[HD + m0] + b_hh[HD + m0];
        const float bias_hi = b_ih[HD + m0 + 8] + b_hh[HD + m0 + 8];

        int avA = 0;
        if (tid == 0) avA = prewait(&g_progA[cid], 32);

        for (int tp = 0; tp < TLEN; tp += 2) {
            if (tid == 0 && avA < tp + 2) {
                while ((avA = ld_acq(&g_progA[cid])) < tp + 2) {}
            }
            __syncthreads();

            // stage two h0 tiles (flat 4KB copies)
            uint2 v0 = *(const uint2*)((const char*)g_H0h +
                        (((size_t)tp * 4 + cid) * 4096) + tid * 8);
            uint2 v1 = *(const uint2*)((const char*)g_H0h +
                        (((size_t)(tp + 1) * 4 + cid) * 4096) + tid * 8);
            *(uint2*)((char*)&hsT[0][0][0] + tid * 8) = v0;
            *(uint2*)((char*)&hsT[1][0][0] + tid * 8) = v1;
            __syncthreads();

            #pragma unroll
            for (int s = 0; s < 2; ++s) {
                float c0[4] = {}, c1[4] = {}, c2[4] = {}, c3[4] = {};
                MMA_STEP16T(c0, c1, c2, c3, afr, lsmT + s * BUFB);
                float4 o;
                o.x = SUM4(0) + bias_lo;
                o.y = SUM4(1) + bias_lo;
                o.z = SUM4(2) + bias_hi;
                o.w = SUM4(3) + bias_hi;
                *(float4*)(g_Xp1 +
                    (((size_t)(tp + s) * 4 + cid) * 16 + w) * 128 + lane * 4) = o;
            }
            __syncthreads();
            if (tid == 0 && (((tp + 2) & 7) == 0 || tp + 2 == TLEN))
                st_rel(&g_progB[cid], tp + 2);
        }
    }
    // ======================= Stage C: layer-1 recurrence ====================
    else {
        uint32_t afr[16][4];
        load_frags16(afr, Whh1, m0, tid4);

        const float* h0l1 = h0all + (size_t)NB * HD;
        for (int idx = tid; idx < 2048; idx += 512) {
            const int k = idx >> 3, n = idx & 7;
            hsT[0][k][n] = __float2half_rn(h0l1[(size_t)(b0 + n) * HD + k]);
        }
        __syncthreads();

        int avB = prewait(&g_progB[cid], 64);
        const size_t fb = ((size_t)cid * 16 + w) * 128 + lane * 4;
        float4 xa = *(const float4*)(g_Xp1 + fb);
        float4 xb = *(const float4*)(g_Xp1 + 8192 + fb);

        for (int u = 0; u <= TLEN; ++u) {
            const int rd = u & 1, wr = rd ^ 1;

            float c0[4] = {}, c1[4] = {}, c2[4] = {}, c3[4] = {};
            if (u < TLEN) MMA_STEP16T(c0, c1, c2, c3, afr, lsmT + rd * BUFB);

            // flush Out(u-1) behind the MMA drain (float4 per thread)
            if (u > 0) {
                const int fn = tid >> 6, fc = (tid & 63) * 4;
                float4 a = *(const float4*)&obuf[rd][fn][fc];
                *(float4*)(Out + ((size_t)(u - 1) * NB + b0 + fn) * HD + fc) = a;
            }

            if (u < TLEN) {
                const int tn = (u + 2 < TLEN) ? u + 2 : TLEN - 1;
                if (avB < tn + 1) {
                    while ((avB = ld_acq(&g_progB[cid])) < tn + 1) {}
                }
                float4 xn = *(const float4*)(g_Xp1 + (size_t)tn * 8192 + fb);

                const float* x = (const float*)&xa;
                float v0 = tanh_mufu(SUM4(0) + x[0]);
                float v1 = tanh_mufu(SUM4(1) + x[1]);
                float v2 = tanh_mufu(SUM4(2) + x[2]);
                float v3 = tanh_mufu(SUM4(3) + x[3]);
                *(uint32_t*)&hsT[wr][m0][n0]     = pack_h2(v0, v1);
                *(uint32_t*)&hsT[wr][m0 + 8][n0] = pack_h2(v2, v3);
                obuf[wr][n0][m0]         = v0;
                obuf[wr][n0 + 1][m0]     = v1;
                obuf[wr][n0][m0 + 8]     = v2;
                obuf[wr][n0 + 1][m0 + 8] = v3;
                xa = xb; xb = xn;
            }
            __syncthreads();
        }
    }
}

// --------------------- input-path GEMM (layer 0, HMMA) ----------------------
// Xp0 = x @ W_ih0^T + biases, fp16 tensor cores, frag-layout output.
// 256 CTAs x 512 threads, 64 tiles each, double-buffered staging.
// Staging: 512 threads cover 4 rows x 128 k-pairs per pass; two passes cover
// rows {sn, sn+4} (sn = tid>>7 in 0..3).
__global__ void __launch_bounds__(512, 1) gemm0_hmma_kernel(
    const float* __restrict__ x, const float* __restrict__ Wih0,
    const float* __restrict__ bi, const float* __restrict__ bh,
    float* __restrict__ OutF)
{
    __shared__ __align__(16) __half xs[2][8][HS];

    const int tid  = threadIdx.x;
    const int w    = tid >> 5;
    const int lane = tid & 31;
    const int grp  = lane >> 2;
    const int m0   = w * 16 + grp;

    if (blockIdx.x == 0 && tid == 0) {
        #pragma unroll
        for (int i = 0; i < 4; ++i) { g_progA[i] = 0; g_progB[i] = 0; }
    }

    uint32_t afr[16][4];
    load_frags16(afr, Wih0, m0, lane & 3);
    const float bias_lo = bi[m0] + bh[m0];
    const float bias_hi = bi[m0 + 8] + bh[m0 + 8];

    const uint32_t xs_base = smem_u32(&xs[0][0][0]);
    const uint32_t lsm = xs_base + (uint32_t)(lane & 7) * (HS * 2) + (uint32_t)(lane >> 3) * 16;
    const uint32_t XBUF = 8 * HS * 2;

    const int sn = tid >> 7, sk = (tid & 127) * 2;   // rows {sn, sn+4}
    const int tile0 = blockIdx.x * 64;               // 16384 tiles / 256 CTAs

    // prologue: stage tile0 into buffer 0
    {
        float2 a0 = *(const float2*)&x[((size_t)tile0 * 8 + sn) * HD + sk];
        float2 a1 = *(const float2*)&x[((size_t)tile0 * 8 + sn + 4) * HD + sk];
        *(uint32_t*)&xs[0][sn][sk]     = pack_h2(a0.x, a0.y);
        *(uint32_t*)&xs[0][sn + 4][sk] = pack_h2(a1.x, a1.y);
    }
    __syncthreads();

    for (int it = 0; it < 64; ++it) {
        const int tile = tile0 + it;
        const int cur = it & 1, nxt = cur ^ 1;

        // prefetch next tile's x into registers (hidden behind the MMAs)
        float2 a0, a1;
        if (it + 1 < 64) {
            const size_t nb = ((size_t)(tile + 1) * 8 + sn) * HD + sk;
            a0 = *(const float2*)&x[nb];
            a1 = *(const float2*)&x[nb + 4 * HD];
        }

        float c0[4] = {}, c1[4] = {}, c2[4] = {}, c3[4] = {};
        MMA_STEP16(c0, c1, c2, c3, afr, lsm + cur * XBUF);

        if (it + 1 < 64) {
            *(uint32_t*)&xs[nxt][sn][sk]     = pack_h2(a0.x, a0.y);
            *(uint32_t*)&xs[nxt][sn + 4][sk] = pack_h2(a1.x, a1.y);
        }

        float4 o;
        o.x = SUM4(0) + bias_lo;
        o.y = SUM4(1) + bias_lo;
        o.z = SUM4(2) + bias_hi;
        o.w = SUM4(3) + bias_hi;
        *(float4*)(OutF + ((size_t)tile * 16 + w) * 128 + lane * 4) = o;
        __syncthreads();
    }
}

// -------------------------------- launcher ----------------------------------
extern "C" void kernel_launch(void* const* d_in, const int* in_sizes, int n_in,
                              void* d_out, int out_size) {
    const float* x    = (const float*)d_in[0];  // [T,B,D]
    const float* W_ih = (const float*)d_in[1];  // [L,H,D]
    const float* W_hh = (const float*)d_in[2];  // [L,H,H]
    const float* b_ih = (const float*)d_in[3];  // [L,H]
    const float* b_hh = (const float*)d_in[4];  // [L,H]
    const float* h0   = (const float*)d_in[5];  // [L,B,H]
    float* out = (float*)d_out;                 // [T,B,H]

    float* Xp0 = nullptr;
    cudaGetSymbolAddress((void**)&Xp0, g_Xp0);

    gemm0_hmma_kernel<<<256, 512>>>(x, W_ih, b_ih, b_hh, Xp0);
    rnn_fused_kernel<<<12, 512>>>(W_hh, W_hh + HD * HD, W_ih + HD * HD,
                                  b_ih, b_hh, h0, out);
}

// round 13
// speedup vs baseline: 2.0176x; 1.1869x over previous
#include <cuda_runtime.h>
#include <cuda_fp16.h>
#include <cstdint>
#include <cstddef>

#define TLEN 4096
#define NB   32
#define HD   256
#define HS   264   // G staging: halves per n-row (256 + 8 pad)

// Scratch (device globals: allocation-free rule)
static __device__ __align__(256) float  g_Xp0[(size_t)TLEN * NB * HD]; // frag-layout preacts L0
static __device__ __align__(256) float  g_Xp1[(size_t)TLEN * NB * HD]; // frag-layout preacts L1
static __device__ __align__(256) __half g_H0h[(size_t)TLEN * NB * HD]; // L0 hidden [t][cid][k][n]
static __device__ int g_progA[4];
static __device__ int g_progB[4];
static __device__ int g_progG[8];   // [par*4 + cid]: count of produced t's of that parity

// ---------------------------------------------------------------------------
__device__ __forceinline__ float tanh_mufu(float x) {
    float y;
    asm("tanh.approx.f32 %0, %1;" : "=f"(y) : "f"(x));
    return y;
}
__device__ __forceinline__ uint32_t pack_h2(float lo, float hi) {
    __half2 h = __floats2half2_rn(lo, hi);
    return *reinterpret_cast<uint32_t*>(&h);
}
__device__ __forceinline__ uint32_t smem_u32(const void* p) {
    uint32_t a;
    asm("{ .reg .u64 t; cvta.to.shared.u64 t, %1; cvt.u32.u64 %0, t; }" : "=r"(a) : "l"(p));
    return a;
}
__device__ __forceinline__ int ld_acq(const int* p) {
    int v;
    asm volatile("ld.acquire.gpu.global.s32 %0, [%1];" : "=r"(v) : "l"(p));
    return v;
}
__device__ __forceinline__ void st_rel(int* p, int v) {
    asm volatile("st.release.gpu.global.s32 [%0], %1;" :: "l"(p), "r"(v));
}
__device__ __forceinline__ int prewait(const int* p, int v) {
    int a;
    while ((a = ld_acq(p)) < v) { __nanosleep(200); }
    return a;
}
#define HMMA(acc, af, bf0, bf1)                                               \
    asm volatile(                                                             \
        "mma.sync.aligned.m16n8k16.row.col.f32.f16.f16.f32 "                  \
        "{%0,%1,%2,%3}, {%4,%5,%6,%7}, {%8,%9}, {%0,%1,%2,%3};"               \
        : "+f"((acc)[0]), "+f"((acc)[1]), "+f"((acc)[2]), "+f"((acc)[3])      \
        : "r"((af)[0]), "r"((af)[1]), "r"((af)[2]), "r"((af)[3]),             \
          "r"(bf0), "r"(bf1))
#define LDSM4(r0, r1, r2, r3, a)                                              \
    asm volatile("ldmatrix.sync.aligned.m8n8.x4.shared.b16 {%0,%1,%2,%3}, [%4];" \
        : "=r"(r0), "=r"(r1), "=r"(r2), "=r"(r3) : "r"(a))
#define LDSM4T(r0, r1, r2, r3, a)                                             \
    asm volatile("ldmatrix.sync.aligned.m8n8.x4.trans.shared.b16 {%0,%1,%2,%3}, [%4];" \
        : "=r"(r0), "=r"(r1), "=r"(r2), "=r"(r3) : "r"(a))

// n-major (G): 8 LDSM4 + 16 HMMA, TWO depth-8 chains.
#define MMA_STEP16_2(c0, c1, afr, ab)                                         \
    do {                                                                      \
        _Pragma("unroll")                                                     \
        for (int kk = 0; kk < 8; ++kk) {                                      \
            uint32_t b0, b1, b2, b3;                                          \
            LDSM4(b0, b1, b2, b3, (ab) + kk * 64);                            \
            HMMA((c0), (afr)[2 * kk],     b0, b1);                            \
            HMMA((c1), (afr)[2 * kk + 1], b2, b3);                            \
        }                                                                     \
    } while (0)

// k-major (scan): 8 LDSM4T + 16 HMMA, TWO depth-8 chains.
#define MMA_STEP16T_2(c0, c1, afr, ab)                                        \
    do {                                                                      \
        _Pragma("unroll")                                                     \
        for (int kk = 0; kk < 8; ++kk) {                                      \
            uint32_t b0, b1, b2, b3;                                          \
            LDSM4T(b0, b1, b2, b3, (ab) + kk * 512);                          \
            HMMA((c0), (afr)[2 * kk],     b0, b1);                            \
            HMMA((c1), (afr)[2 * kk + 1], b2, b3);                            \
        }                                                                     \
    } while (0)

// Register-resident A fragments for rows (r0, r0+8) of a 256x256 fp32 weight.
__device__ __forceinline__ void load_frags16(uint32_t afr[16][4],
                                             const float* __restrict__ W,
                                             int r0, int tid4) {
    #pragma unroll
    for (int kt = 0; kt < 16; ++kt) {
        const int k0 = kt * 16 + tid4 * 2;
        const float* p0 = W + (size_t)r0 * HD + k0;
        const float* p1 = W + (size_t)(r0 + 8) * HD + k0;
        afr[kt][0] = pack_h2(p0[0], p0[1]);
        afr[kt][1] = pack_h2(p1[0], p1[1]);
        afr[kt][2] = pack_h2(p0[8], p0[9]);
        afr[kt][3] = pack_h2(p1[8], p1[9]);
    }
}

// ---------------------------------------------------------------------------
// Flag reset (flags persist across graph replays; must run before fused kernel)
__global__ void reset_flags_kernel() {
    const int t = threadIdx.x;
    if (t < 4) { g_progA[t] = 0; g_progB[t] = 0; }
    if (t < 8) g_progG[t] = 0;
}

// ---------------------------------------------------------------------------
// Fused 4-stage pipelined kernel.  grid = 20 CTAs x 512 threads (16 warps):
//   CTA 0-3  (A): layer-0 recurrence     CTA 4-7  (B): xp1 projection
//   CTA 8-11 (C): layer-1 recurrence     CTA 12-19(G): xp0 input GEMM (t-ordered)
__global__ void __launch_bounds__(512, 1) rnn_fused_kernel(
    const float* __restrict__ xin,  const float* __restrict__ Wih0,
    const float* __restrict__ Whh0, const float* __restrict__ Whh1,
    const float* __restrict__ Wih1,
    const float* __restrict__ b_ih, const float* __restrict__ b_hh,
    const float* __restrict__ h0all, float* __restrict__ Out)
{
    __shared__ __align__(16) __half hsT[2][256][8];  // scan h state (k-major)
    __shared__ __align__(16) float  obuf[2][8][260]; // C: output staging
    __shared__ __align__(16) __half xs[2][8][HS];    // G: x staging

    const int bx   = blockIdx.x;
    const int tid  = threadIdx.x;
    const int w    = tid >> 5;
    const int lane = tid & 31;
    const int grp  = lane >> 2;
    const int tid4 = lane & 3;
    const int role = (bx < 12) ? (bx >> 2) : 3;   // 0=A,1=B,2=C,3=G
    const int cid  = bx & 3;
    const int b0   = cid * 8;
    const int m0   = w * 16 + grp;
    const int n0   = tid4 * 2;

    const uint32_t hs_base = smem_u32(&hsT[0][0][0]);
    const uint32_t lsmT = hs_base + (uint32_t)lane * 16;
    const uint32_t BUFB = 4096;

    // ======================= Stage A: layer-0 recurrence ====================
    if (role == 0) {
        uint32_t afr[16][4];
        load_frags16(afr, Whh0, m0, tid4);

        for (int idx = tid; idx < 2048; idx += 512) {
            const int k = idx >> 3, n = idx & 7;
            hsT[0][k][n] = __float2half_rn(h0all[(size_t)(b0 + n) * HD + k]);
        }
        __syncthreads();

        // skid: wait for G to produce 16 t's per parity (t < 32 available)
        int avG[2];
        avG[0] = prewait(&g_progG[cid], 16);
        avG[1] = prewait(&g_progG[4 + cid], 16);

        const size_t fb = ((size_t)cid * 16 + w) * 128 + lane * 4;
        float4 xa = *(const float4*)(g_Xp0 + fb);           // x(0)
        float4 xb = *(const float4*)(g_Xp0 + 8192 + fb);    // x(1)

        for (int u = 0; u <= TLEN; ++u) {
            const int rd = u & 1, wr = rd ^ 1;

            float c0[4], c1[4] = {};
            const float* x = (const float*)&xa;
            c0[0] = x[0]; c0[1] = x[1]; c0[2] = x[2]; c0[3] = x[3];
            if (u < TLEN) MMA_STEP16T_2(c0, c1, afr, lsmT + rd * BUFB);

            // publish h0(u-1) behind the MMA drain (flat 4KB copy)
            if (u > 0) {
                uint2 v = *(const uint2*)((const char*)&hsT[rd][0][0] + tid * 8);
                *(uint2*)((char*)g_H0h +
                          (((size_t)(u - 1) * 4 + cid) * 4096) + tid * 8) = v;
            }

            if (u < TLEN) {
                const int tn = (u + 2 < TLEN) ? u + 2 : TLEN - 1;
                const int par = tn & 1, ii = tn >> 1;
                if (avG[par] <= ii) {
                    while ((avG[par] = ld_acq(&g_progG[par * 4 + cid])) <= ii) {}
                }
                float4 xn = *(const float4*)(g_Xp0 + (size_t)tn * 8192 + fb);

                float v0 = tanh_mufu(c0[0] + c1[0]);   // (m0,   n0)
                float v1 = tanh_mufu(c0[1] + c1[1]);   // (m0,   n0+1)
                float v2 = tanh_mufu(c0[2] + c1[2]);   // (m0+8, n0)
                float v3 = tanh_mufu(c0[3] + c1[3]);   // (m0+8, n0+1)
                *(uint32_t*)&hsT[wr][m0][n0]     = pack_h2(v0, v1);
                *(uint32_t*)&hsT[wr][m0 + 8][n0] = pack_h2(v2, v3);
                xa = xb; xb = xn;
            }
            __syncthreads();
            if (tid == 0 && u > 0 && ((u & 3) == 0 || u == TLEN))
                st_rel(&g_progA[cid], u);
        }
    }
    // ======================= Stage B: xp1 projection ========================
    else if (role == 1) {
        uint32_t afr[16][4];
        load_frags16(afr, Wih1, m0, tid4);
        const float bias_lo = b_ih[HD + m0] + b_hh[HD + m0];
        const float bias_hi = b_ih[HD + m0 + 8] + b_hh[HD + m0 + 8];

        int avA = 0;
        if (tid == 0) avA = prewait(&g_progA[cid], 32);

        for (int tp = 0; tp < TLEN; tp += 2) {
            if (tid == 0 && avA < tp + 2) {
                while ((avA = ld_acq(&g_progA[cid])) < tp + 2) {}
            }
            __syncthreads();

            // stage two h0 tiles (flat 4KB copies)
            uint2 v0 = *(const uint2*)((const char*)g_H0h +
                        (((size_t)tp * 4 + cid) * 4096) + tid * 8);
            uint2 v1 = *(const uint2*)((const char*)g_H0h +
                        (((size_t)(tp + 1) * 4 + cid) * 4096) + tid * 8);
            *(uint2*)((char*)&hsT[0][0][0] + tid * 8) = v0;
            *(uint2*)((char*)&hsT[1][0][0] + tid * 8) = v1;
            __syncthreads();

            #pragma unroll
            for (int s = 0; s < 2; ++s) {
                float c0[4], c1[4] = {};
                c0[0] = bias_lo; c0[1] = bias_lo; c0[2] = bias_hi; c0[3] = bias_hi;
                MMA_STEP16T_2(c0, c1, afr, lsmT + s * BUFB);
                float4 o;
                o.x = c0[0] + c1[0];
                o.y = c0[1] + c1[1];
                o.z = c0[2] + c1[2];
                o.w = c0[3] + c1[3];
                *(float4*)(g_Xp1 +
                    (((size_t)(tp + s) * 4 + cid) * 16 + w) * 128 + lane * 4) = o;
            }
            __syncthreads();
            if (tid == 0 && (((tp + 2) & 7) == 0 || tp + 2 == TLEN))
                st_rel(&g_progB[cid], tp + 2);
        }
    }
    // ======================= Stage C: layer-1 recurrence ====================
    else if (role == 2) {
        uint32_t afr[16][4];
        load_frags16(afr, Whh1, m0, tid4);

        const float* h0l1 = h0all + (size_t)NB * HD;
        for (int idx = tid; idx < 2048; idx += 512) {
            const int k = idx >> 3, n = idx & 7;
            hsT[0][k][n] = __float2half_rn(h0l1[(size_t)(b0 + n) * HD + k]);
        }
        __syncthreads();

        int avB = prewait(&g_progB[cid], 64);
        const size_t fb = ((size_t)cid * 16 + w) * 128 + lane * 4;
        float4 xa = *(const float4*)(g_Xp1 + fb);
        float4 xb = *(const float4*)(g_Xp1 + 8192 + fb);

        for (int u = 0; u <= TLEN; ++u) {
            const int rd = u & 1, wr = rd ^ 1;

            float c0[4], c1[4] = {};
            const float* x = (const float*)&xa;
            c0[0] = x[0]; c0[1] = x[1]; c0[2] = x[2]; c0[3] = x[3];
            if (u < TLEN) MMA_STEP16T_2(c0, c1, afr, lsmT + rd * BUFB);

            // flush Out(u-1) behind the MMA drain (float4 per thread)
            if (u > 0) {
                const int fn = tid >> 6, fc = (tid & 63) * 4;
                float4 a = *(const float4*)&obuf[rd][fn][fc];
                *(float4*)(Out + ((size_t)(u - 1) * NB + b0 + fn) * HD + fc) = a;
            }

            if (u < TLEN) {
                const int tn = (u + 2 < TLEN) ? u + 2 : TLEN - 1;
                if (avB < tn + 1) {
                    while ((avB = ld_acq(&g_progB[cid])) < tn + 1) {}
                }
                float4 xn = *(const float4*)(g_Xp1 + (size_t)tn * 8192 + fb);

                float v0 = tanh_mufu(c0[0] + c1[0]);
                float v1 = tanh_mufu(c0[1] + c1[1]);
                float v2 = tanh_mufu(c0[2] + c1[2]);
                float v3 = tanh_mufu(c0[3] + c1[3]);
                *(uint32_t*)&hsT[wr][m0][n0]     = pack_h2(v0, v1);
                *(uint32_t*)&hsT[wr][m0 + 8][n0] = pack_h2(v2, v3);
                obuf[wr][n0][m0]         = v0;
                obuf[wr][n0 + 1][m0]     = v1;
                obuf[wr][n0][m0 + 8]     = v2;
                obuf[wr][n0 + 1][m0 + 8] = v3;
                xa = xb; xb = xn;
            }
            __syncthreads();
        }
    }
    // ======================= Stage G: xp0 input GEMM ========================
    else {
        const int j    = bx - 12;      // 0..7
        const int gcid = j & 3;
        const int par  = j >> 2;       // t parity this CTA produces

        uint32_t afr[16][4];
        load_frags16(afr, Wih0, m0, tid4);
        const float bias_lo = b_ih[m0] + b_hh[m0];
        const float bias_hi = b_ih[m0 + 8] + b_hh[m0 + 8];

        const uint32_t xs_base = smem_u32(&xs[0][0][0]);
        const uint32_t lsm = xs_base + (uint32_t)(lane & 7) * (HS * 2)
                                     + (uint32_t)(lane >> 3) * 16;
        const uint32_t XBUF = 8 * HS * 2;

        const int sn = tid >> 7, sk = (tid & 127) * 2;   // rows {sn, sn+4}
        int tile = par * 4 + gcid;                       // t = par

        // prologue: stage first tile into buffer 0
        {
            float2 a0 = *(const float2*)&xin[((size_t)tile * 8 + sn) * HD + sk];
            float2 a1 = *(const float2*)&xin[((size_t)tile * 8 + sn + 4) * HD + sk];
            *(uint32_t*)&xs[0][sn][sk]     = pack_h2(a0.x, a0.y);
            *(uint32_t*)&xs[0][sn + 4][sk] = pack_h2(a1.x, a1.y);
        }
        __syncthreads();

        for (int it = 0; it < 2048; ++it) {
            const int cur = it & 1, nxt = cur ^ 1;

            float2 a0, a1;
            if (it + 1 < 2048) {
                const size_t nb = ((size_t)(tile + 8) * 8 + sn) * HD + sk;
                a0 = *(const float2*)&xin[nb];
                a1 = *(const float2*)&xin[nb + 4 * HD];
            }

            float c0[4], c1[4] = {};
            c0[0] = bias_lo; c0[1] = bias_lo; c0[2] = bias_hi; c0[3] = bias_hi;
            MMA_STEP16_2(c0, c1, afr, lsm + cur * XBUF);

            if (it + 1 < 2048) {
                *(uint32_t*)&xs[nxt][sn][sk]     = pack_h2(a0.x, a0.y);
                *(uint32_t*)&xs[nxt][sn + 4][sk] = pack_h2(a1.x, a1.y);
            }

            float4 o;
            o.x = c0[0] + c1[0];
            o.y = c0[1] + c1[1];
            o.z = c0[2] + c1[2];
            o.w = c0[3] + c1[3];
            *(float4*)(g_Xp0 + ((size_t)tile * 16 + w) * 128 + lane * 4) = o;
            __syncthreads();
            if (tid == 0 && (((it + 1) & 3) == 0 || it + 1 == 2048))
                st_rel(&g_progG[j], it + 1);
            tile += 8;   // next t of this parity
        }
    }
}

// -------------------------------- launcher ----------------------------------
extern "C" void kernel_launch(void* const* d_in, const int* in_sizes, int n_in,
                              void* d_out, int out_size) {
    const float* x    = (const float*)d_in[0];  // [T,B,D]
    const float* W_ih = (const float*)d_in[1];  // [L,H,D]
    const float* W_hh = (const float*)d_in[2];  // [L,H,H]
    const float* b_ih = (const float*)d_in[3];  // [L,H]
    const float* b_hh = (const float*)d_in[4];  // [L,H]
    const float* h0   = (const float*)d_in[5];  // [L,B,H]
    float* out = (float*)d_out;                 // [T,B,H]

    reset_flags_kernel<<<1, 32>>>();
    rnn_fused_kernel<<<20, 512>>>(x, W_ih,
                                  W_hh, W_hh + HD * HD, W_ih + HD * HD,
                                  b_ih, b_hh, h0, out);
}